// round 15
// baseline (speedup 1.0000x reference)
#include <cuda_runtime.h>
#include <cuda_bf16.h>
#include <cstdint>
#include <math.h>

// Problem constants
#define Bc   64
#define Tc   512
#define Fc   128
#define Hc   512
#define G4   2048
#define Nf   32768          // flattened (t,b) columns = Tc*Bc
#define NCTA 128            // persistent CTAs for recurrent kernel

// ---------------------------------------------------------------------------
// Scratch (device globals)
// ---------------------------------------------------------------------------
__device__ __align__(16) float         g_xproj[(size_t)G4 * Nf];      // [2048][32768] 256 MB
__device__ __align__(16) __nv_bfloat16 g_hsHi[(size_t)Nf * Hc];       // [t*64+b][u]
__device__ __align__(16) __nv_bfloat16 g_hsLo[(size_t)Nf * Hc];
__device__ __align__(16) __nv_bfloat16 g_Whi[(size_t)G4 * Hc];        // reused per layer
__device__ __align__(16) __nv_bfloat16 g_Wlo[(size_t)G4 * Hc];
__device__ __align__(16) __nv_bfloat16 g_Xhi[(size_t)Nf * Fc];        // layer-0 input
__device__ __align__(16) __nv_bfloat16 g_Xlo[(size_t)Nf * Fc];
__device__ __align__(16) __nv_bfloat16 g_hHiT[2][Bc * Hc];            // h ping-pong [buf][b][u]
__device__ __align__(16) __nv_bfloat16 g_hLoT[2][Bc * Hc];
__device__ __align__(16) float         g_h1[64 * Bc];
__device__ unsigned g_barGen;                 // closing (atomic) barrier state
__device__ unsigned g_barCount;
__device__ __align__(128) unsigned g_arr[NCTA * 8];   // per-CTA arrival flags (32B padded)

// ---------------------------------------------------------------------------
// PTX helpers (arch-agnostic ISA only: valid at compute_103)
// ---------------------------------------------------------------------------
__device__ __forceinline__ uint32_t smem_u32(const void* p) {
    uint32_t a;
    asm("{ .reg .u64 t; cvta.to.shared.u64 t, %1; cvt.u32.u64 %0, t; }" : "=r"(a) : "l"(p));
    return a;
}
#define CPA(dst, src)  asm volatile("cp.async.ca.shared.global [%0], [%1], 16;" :: "r"(dst), "l"(src))
#define CPCOMMIT()    asm volatile("cp.async.commit_group;" ::: "memory")
#define CPWAIT0()     asm volatile("cp.async.wait_group 0;" ::: "memory")
#define CPWAIT1()     asm volatile("cp.async.wait_group 1;" ::: "memory")

__device__ __forceinline__ void ldsm4(uint32_t* r, uint32_t a) {
    asm volatile("ldmatrix.sync.aligned.m8n8.x4.shared.b16 {%0,%1,%2,%3}, [%4];"
                 : "=r"(r[0]), "=r"(r[1]), "=r"(r[2]), "=r"(r[3]) : "r"(a));
}
__device__ __forceinline__ void mma16816(float* c, const uint32_t* a, uint32_t b0, uint32_t b1) {
    asm volatile("mma.sync.aligned.m16n8k16.row.col.f32.bf16.bf16.f32 "
                 "{%0,%1,%2,%3}, {%4,%5,%6,%7}, {%8,%9}, {%0,%1,%2,%3};"
                 : "+f"(c[0]), "+f"(c[1]), "+f"(c[2]), "+f"(c[3])
                 : "r"(a[0]), "r"(a[1]), "r"(a[2]), "r"(a[3]), "r"(b0), "r"(b1));
}
__device__ __forceinline__ uint32_t ldcg_u32(const void* p) {
    uint32_t v;
    asm volatile("ld.global.cg.b32 %0, [%1];" : "=r"(v) : "l"(p));
    return v;
}
__device__ __forceinline__ void splitpack(float x0, float x1, uint32_t& hi, uint32_t& lo) {
    __nv_bfloat16 h0 = __float2bfloat16(x0);
    __nv_bfloat16 h1 = __float2bfloat16(x1);
    __nv_bfloat16 e0 = __float2bfloat16(x0 - __bfloat162float(h0));
    __nv_bfloat16 e1 = __float2bfloat16(x1 - __bfloat162float(h1));
    hi = (uint32_t)__bfloat16_as_ushort(h0) | ((uint32_t)__bfloat16_as_ushort(h1) << 16);
    lo = (uint32_t)__bfloat16_as_ushort(e0) | ((uint32_t)__bfloat16_as_ushort(e1) << 16);
}
// bounded-backoff spin: tight for 4096 iters, then nanosleep to cap L2 pressure
__device__ __forceinline__ void spin_wait(volatile unsigned* f, unsigned v) {
    int it = 0;
    while (*f < v) {
        if (++it > 4096) __nanosleep(64);
    }
}

// ---------------------------------------------------------------------------
// fp32 -> bf16 hi/lo split
// ---------------------------------------------------------------------------
__global__ void split_bf16(const float* __restrict__ src,
                           __nv_bfloat16* __restrict__ hi,
                           __nv_bfloat16* __restrict__ lo, int n)
{
    int i = blockIdx.x * 256 + threadIdx.x;
    if (i < n) {
        float x = src[i];
        __nv_bfloat16 h = __float2bfloat16(x);
        hi[i] = h;
        lo[i] = __float2bfloat16(x - __bfloat162float(h));
    }
}

// ---------------------------------------------------------------------------
// Tensor-core (mma.sync bf16) xproj GEMM (unchanged, verified):
//   out[g][n] = sum_k W[g,k]*X[n,k] + bih[g]+bhh[g]
// ---------------------------------------------------------------------------
#define OFF_AH 0u
#define OFF_AL 16384u
#define OFF_BH 32768u
#define OFF_BL 49152u
#define BUFSTR 65536u
#define GEMM_SMEM (2u * BUFSTR)   // 131072 bytes

__device__ __forceinline__ void gemm_issue(
    uint32_t base, const __nv_bfloat16* __restrict__ Ahi, const __nv_bfloat16* __restrict__ Alo,
    const __nv_bfloat16* __restrict__ Bhi, const __nv_bfloat16* __restrict__ Blo,
    int g0, int n0, int kb, int K, int tid)
{
#pragma unroll
    for (int j = 0; j < 4; ++j) {
        int i = tid + j * 256;          // 0..1023
        int r = i >> 3;                 // 0..127
        int c16 = i & 7;                // 16B chunk within 128B row
        uint32_t so = (uint32_t)(r * 128 + ((c16 ^ (r & 7)) << 4));
        size_t ga = (size_t)(g0 + r) * K + kb + c16 * 8;
        size_t gb = (size_t)(n0 + r) * K + kb + c16 * 8;
        CPA(base + OFF_AH + so, Ahi + ga);
        CPA(base + OFF_AL + so, Alo + ga);
        CPA(base + OFF_BH + so, Bhi + gb);
        CPA(base + OFF_BL + so, Blo + gb);
    }
}

__global__ void __launch_bounds__(256, 1)
gemm_tc(const __nv_bfloat16* __restrict__ Ahi, const __nv_bfloat16* __restrict__ Alo,
        const __nv_bfloat16* __restrict__ Bhi, const __nv_bfloat16* __restrict__ Blo,
        const float* __restrict__ bih, const float* __restrict__ bhh,
        float* __restrict__ out, int K)
{
    extern __shared__ char smem[];
    const uint32_t sb = smem_u32(smem);
    const int tid = threadIdx.x, wid = tid >> 5, lid = tid & 31;
    const int g0 = blockIdx.x * 128;
    const int n0 = blockIdx.y * 128;
    const int wm = wid & 1;             // 0..1  -> 64 rows
    const int wn = wid >> 1;            // 0..3  -> 32 cols

    float acc[4][4][4];
#pragma unroll
    for (int a = 0; a < 4; ++a)
#pragma unroll
        for (int b = 0; b < 4; ++b)
#pragma unroll
            for (int c = 0; c < 4; ++c) acc[a][b][c] = 0.f;

    const int nk = K >> 6;

    gemm_issue(sb, Ahi, Alo, Bhi, Blo, g0, n0, 0, K, tid);
    CPCOMMIT();

    const int lrow = lid & 15;
    const int lchunk = lid >> 4;        // 0..1 -> +16B

    for (int kc = 0; kc < nk; ++kc) {
        if (kc + 1 < nk) {
            gemm_issue(sb + ((kc + 1) & 1) * BUFSTR, Ahi, Alo, Bhi, Blo,
                       g0, n0, (kc + 1) << 6, K, tid);
            CPCOMMIT();
            CPWAIT1();
        } else {
            CPWAIT0();
        }
        __syncthreads();

        const uint32_t buf = sb + (kc & 1) * BUFSTR;
#pragma unroll
        for (int ks = 0; ks < 4; ++ks) {
            const int c16 = ks * 2 + lchunk;
            uint32_t ah[4][4], al[4][4];
#pragma unroll
            for (int mt = 0; mt < 4; ++mt) {
                int row = wm * 64 + mt * 16 + lrow;
                uint32_t so = (uint32_t)(row * 128 + ((c16 ^ (row & 7)) << 4));
                ldsm4(ah[mt], buf + OFF_AH + so);
                ldsm4(al[mt], buf + OFF_AL + so);
            }
            uint32_t bh[2][4], bl[2][4];
#pragma unroll
            for (int hlf = 0; hlf < 2; ++hlf) {
                int row = wn * 32 + hlf * 16 + lrow;
                uint32_t so = (uint32_t)(row * 128 + ((c16 ^ (row & 7)) << 4));
                ldsm4(bh[hlf], buf + OFF_BH + so);
                ldsm4(bl[hlf], buf + OFF_BL + so);
            }
#pragma unroll
            for (int mt = 0; mt < 4; ++mt) {
#pragma unroll
                for (int nt = 0; nt < 4; ++nt) {
                    const int hlf = nt >> 1, ix = nt & 1;
                    mma16816(acc[mt][nt], ah[mt], bh[hlf][ix], bh[hlf][ix + 2]);
                    mma16816(acc[mt][nt], ah[mt], bl[hlf][ix], bl[hlf][ix + 2]);
                    mma16816(acc[mt][nt], al[mt], bh[hlf][ix], bh[hlf][ix + 2]);
                }
            }
        }
        __syncthreads();
    }

    const int colb = n0 + wn * 32 + (lid & 3) * 2;
#pragma unroll
    for (int mt = 0; mt < 4; ++mt) {
        int gA = g0 + wm * 64 + mt * 16 + (lid >> 2);
        int gB = gA + 8;
        float biasA = __ldg(bih + gA) + __ldg(bhh + gA);
        float biasB = __ldg(bih + gB) + __ldg(bhh + gB);
        float* pA = out + (size_t)gA * Nf + colb;
        float* pB = out + (size_t)gB * Nf + colb;
#pragma unroll
        for (int nt = 0; nt < 4; ++nt) {
            float2 vA = make_float2(acc[mt][nt][0] + biasA, acc[mt][nt][1] + biasA);
            float2 vB = make_float2(acc[mt][nt][2] + biasB, acc[mt][nt][3] + biasB);
            *(float2*)(pA + nt * 8) = vA;
            *(float2*)(pB + nt * 8) = vB;
        }
    }
}

// ---------------------------------------------------------------------------
// Closing atomic grid barrier (sense-reversal, state-relative -> replay-safe).
// ---------------------------------------------------------------------------
__device__ __forceinline__ void grid_barrier_atomic()
{
    __syncthreads();
    if (threadIdx.x == 0) {
        __threadfence();
        volatile unsigned* vgen = &g_barGen;
        unsigned gen = *vgen;
        unsigned ticket = atomicAdd(&g_barCount, 1u);
        if (ticket == NCTA - 1) {
            g_barCount = 0;
            __threadfence();
            *vgen = gen + 1u;
        } else {
            int it = 0;
            while (*vgen == gen) { if (++it > 4096) __nanosleep(64); }
            __threadfence();
        }
    }
    __syncthreads();
}

__device__ __forceinline__ float sigmoidf_(float x) { return 1.f / (1.f + __expf(-x)); }

// ---------------------------------------------------------------------------
// Persistent recurrent kernel v3: per-warp producer polling, register-resident
// W fragments, B fragments loaded straight from global (ld.global.cg.b32).
//
// CTA c owns units u0=4c..4c+3 (16 gate rows). Warp w owns K-slice
// [64w, 64w+64) = units produced by CTAs 16w..16w+15: it polls exactly those
// 16 flags, then loads its B fragments directly from the h ping-pong and runs
// 96 HMMA (3-term bf16 split). Partials reduced through smem; c state in
// registers; h published as bf16 hi/lo; flag = monotonic step value.
// No central barrier, no cp.async staging, one L2 hop of sync per step.
// WAR safety: CTA c writes buffer t&1 at end of step t+1, gated (via the
// reduce __syncthreads) on all 8 warps' polls >= t+2, whose union covers all
// 128 CTAs -> every reader of buffer t&1 (step t) has finished.
// ---------------------------------------------------------------------------
__global__ void __launch_bounds__(256, 1)
lstm_rec(const float* __restrict__ xproj, const float* __restrict__ Whh,
         __nv_bfloat16* __restrict__ hsHi, __nv_bfloat16* __restrict__ hsLo, int l0)
{
    __shared__ float sRed[8 * 1056];    // 8 warps x [16][66]

    const int tid = threadIdx.x;
    const int w   = tid >> 5;
    const int l   = tid & 31;
    const int cta = blockIdx.x;
    const int u0  = cta << 2;
    const int eb  = tid >> 2;       // elementwise: batch
    const int eu  = tid & 3;        // elementwise: unit offset
    const int u   = u0 + eu;

    const int r  = l >> 2;          // fragment quad-row 0..7
    const int kq = (l & 3) * 2;     // fragment k offset
    const int kb = w * 64;          // warp K-slice base

    // ---- A (W_hh) fragments: register-resident for the whole kernel ----
    uint32_t aHi[4][4], aLo[4][4];
    {
        const float* w0 = Whh + (size_t)((r >> 2) * Hc + u0 + (r & 3)) * Hc;
        const int r1 = r + 8;
        const float* w1 = Whh + (size_t)((r1 >> 2) * Hc + u0 + (r1 & 3)) * Hc;
#pragma unroll
        for (int kt = 0; kt < 4; ++kt) {
            int k0 = kb + kt * 16 + kq;
            splitpack(w0[k0],     w0[k0 + 1], aHi[kt][0], aLo[kt][0]);
            splitpack(w1[k0],     w1[k0 + 1], aHi[kt][1], aLo[kt][1]);
            splitpack(w0[k0 + 8], w0[k0 + 9], aHi[kt][2], aLo[kt][2]);
            splitpack(w1[k0 + 8], w1[k0 + 9], aHi[kt][3], aLo[kt][3]);
        }
    }

    // zero h buffer 0 (our slice)
    g_hHiT[0][eb * Hc + u] = __float2bfloat16(0.f);
    g_hLoT[0][eb * Hc + u] = __float2bfloat16(0.f);

    float c_reg = 0.f;
    // prefetch xproj for t=0
    float xp[4];
    {
        int nidx = l0 ? (eb * 512) : eb;
#pragma unroll
        for (int gt = 0; gt < 4; ++gt)
            xp[gt] = __ldcs(xproj + (size_t)(gt * Hc + u) * Nf + nidx);
    }

    // publish flag = 1 : "h buffer 0 ready"
    __threadfence();
    __syncthreads();
    if (tid == 0) *(volatile unsigned*)&g_arr[cta * 8] = 1u;

    float* sRedW = sRed + w * 1056;

    for (int t = 0; t < Tc; ++t) {
        // ---- poll this warp's 16 producers (one L2 hop, no central barrier) ----
        const unsigned v = (unsigned)(t + 1);
        if (l < 16) spin_wait(&g_arr[(w * 16 + l) * 8], v);
        __syncwarp();
        __threadfence();    // acquire: order fragment loads after the poll

        // ---- B fragments straight from global; 96 HMMA ----
        float acc[8][4];
#pragma unroll
        for (int nb = 0; nb < 8; ++nb)
#pragma unroll
            for (int c = 0; c < 4; ++c) acc[nb][c] = 0.f;

        const __nv_bfloat16* hHi = g_hHiT[t & 1];
        const __nv_bfloat16* hLo = g_hLoT[t & 1];
#pragma unroll
        for (int kt = 0; kt < 4; ++kt) {
            const int ku = kb + kt * 16 + kq;
#pragma unroll
            for (int nb = 0; nb < 8; ++nb) {
                const __nv_bfloat16* ph = hHi + (nb * 8 + r) * Hc + ku;
                const __nv_bfloat16* pl = hLo + (nb * 8 + r) * Hc + ku;
                uint32_t bh0 = ldcg_u32(ph);
                uint32_t bh1 = ldcg_u32(ph + 8);
                uint32_t bl0 = ldcg_u32(pl);
                uint32_t bl1 = ldcg_u32(pl + 8);
                mma16816(acc[nb], aHi[kt], bh0, bh1);
                mma16816(acc[nb], aLo[kt], bh0, bh1);
                mma16816(acc[nb], aHi[kt], bl0, bl1);
            }
        }

        // ---- warp partials -> smem ----
#pragma unroll
        for (int nb = 0; nb < 8; ++nb) {
            int cc = nb * 8 + (l & 3) * 2;
            *(float2*)(sRedW + r * 66 + cc)       = make_float2(acc[nb][0], acc[nb][1]);
            *(float2*)(sRedW + (r + 8) * 66 + cc) = make_float2(acc[nb][2], acc[nb][3]);
        }
        __syncthreads();

        // ---- reduce + elementwise (thread = (eu, eb)) ----
        float gate[4];
#pragma unroll
        for (int gt = 0; gt < 4; ++gt) {
            float s = 0.f;
            int roff = (gt * 4 + eu) * 66 + eb;
#pragma unroll
            for (int ww = 0; ww < 8; ++ww)
                s += sRed[ww * 1056 + roff];
            gate[gt] = s + xp[gt];
        }
        float gi = sigmoidf_(gate[0]);
        float gf = sigmoidf_(gate[1]);
        float gg = tanhf(gate[2]);
        float go = sigmoidf_(gate[3]);
        c_reg = gf * c_reg + gi * gg;
        float hv = go * tanhf(c_reg);

        __nv_bfloat16 hh = __float2bfloat16(hv);
        __nv_bfloat16 hl = __float2bfloat16(hv - __bfloat162float(hh));
        int nxt = (t + 1) & 1;
        g_hHiT[nxt][eb * Hc + u] = hh;
        g_hLoT[nxt][eb * Hc + u] = hl;

        // ---- publish flag (all threads' h stores ordered before it) ----
        __threadfence();
        __syncthreads();
        if (tid == 0) *(volatile unsigned*)&g_arr[cta * 8] = v + 1u;

        // ---- overlapped with flag propagation: hsOut + next xproj prefetch ----
        size_t hsi = ((size_t)t * 64 + eb) * Hc + u;
        hsHi[hsi] = hh;
        hsLo[hsi] = hl;
        if (t + 1 < Tc) {
            int nidx = l0 ? (eb * 512 + t + 1) : ((t + 1) * 64 + eb);
#pragma unroll
            for (int gt = 0; gt < 4; ++gt)
                xp[gt] = __ldcs(xproj + (size_t)(gt * Hc + u) * Nf + nidx);
        }
    }

    // ---- closing: all CTAs done, then reset flags for the next launch ----
    grid_barrier_atomic();
    if (tid == 0) g_arr[cta * 8] = 0u;
}

// ---------------------------------------------------------------------------
// FC head (reads last-step h from bf16 hi/lo)
// ---------------------------------------------------------------------------
__global__ void fc1_kernel(const __nv_bfloat16* __restrict__ hsHi,
                           const __nv_bfloat16* __restrict__ hsLo,
                           const float* __restrict__ W1, const float* __restrict__ b1,
                           float* __restrict__ h1)
{
    int idx = blockIdx.x * 256 + threadIdx.x;   // 0..4095
    int j = idx >> 6;
    int b = idx & 63;
    const __nv_bfloat16* ph = hsHi + ((size_t)(Tc - 1) * 64 + b) * Hc;
    const __nv_bfloat16* pl = hsLo + ((size_t)(Tc - 1) * 64 + b) * Hc;
    float v = b1[j];
    for (int h = 0; h < Hc; ++h)
        v += W1[j * Hc + h] * (__bfloat162float(ph[h]) + __bfloat162float(pl[h]));
    h1[j * 64 + b] = fmaxf(v, 0.f);
}

__global__ void fc2_kernel(const float* __restrict__ h1,
                           const float* __restrict__ W2, const float* __restrict__ b2,
                           float* __restrict__ out)
{
    int b = threadIdx.x;
    float v = b2[0];
    for (int j = 0; j < 64; ++j)
        v += W2[j] * h1[j * 64 + b];
    out[b] = fmaxf(v, 0.f);
}

// ---------------------------------------------------------------------------
// Launch
// ---------------------------------------------------------------------------
extern "C" void kernel_launch(void* const* d_in, const int* in_sizes, int n_in,
                              void* d_out, int out_size)
{
    const float* x    = (const float*)d_in[0];
    const float* Wih0 = (const float*)d_in[1];
    const float* Whh0 = (const float*)d_in[2];
    const float* bih0 = (const float*)d_in[3];
    const float* bhh0 = (const float*)d_in[4];
    const float* Wih1 = (const float*)d_in[5];
    const float* Whh1 = (const float*)d_in[6];
    const float* bih1 = (const float*)d_in[7];
    const float* bhh1 = (const float*)d_in[8];
    const float* Wih2 = (const float*)d_in[9];
    const float* Whh2 = (const float*)d_in[10];
    const float* bih2 = (const float*)d_in[11];
    const float* bhh2 = (const float*)d_in[12];
    const float* W1   = (const float*)d_in[13];
    const float* b1   = (const float*)d_in[14];
    const float* W2   = (const float*)d_in[15];
    const float* b2   = (const float*)d_in[16];

    float *xproj, *h1;
    __nv_bfloat16 *hsHi, *hsLo, *Whi, *Wlo, *Xhi, *Xlo;
    cudaGetSymbolAddress((void**)&xproj, g_xproj);
    cudaGetSymbolAddress((void**)&h1,   g_h1);
    cudaGetSymbolAddress((void**)&hsHi, g_hsHi);
    cudaGetSymbolAddress((void**)&hsLo, g_hsLo);
    cudaGetSymbolAddress((void**)&Whi,  g_Whi);
    cudaGetSymbolAddress((void**)&Wlo,  g_Wlo);
    cudaGetSymbolAddress((void**)&Xhi,  g_Xhi);
    cudaGetSymbolAddress((void**)&Xlo,  g_Xlo);

    cudaFuncSetAttribute(gemm_tc, cudaFuncAttributeMaxDynamicSharedMemorySize, GEMM_SMEM);

    dim3 gg(16, 256);

    // ---- Layer 0 (K = 128; xproj columns n = b*512 + t) ----
    split_bf16<<<(G4 * Fc + 255) / 256, 256>>>(Wih0, Whi, Wlo, G4 * Fc);
    split_bf16<<<(Nf * Fc + 255) / 256, 256>>>(x, Xhi, Xlo, Nf * Fc);
    gemm_tc<<<gg, 256, GEMM_SMEM>>>(Whi, Wlo, Xhi, Xlo, bih0, bhh0, xproj, Fc);
    lstm_rec<<<NCTA, 256>>>(xproj, Whh0, hsHi, hsLo, 1);

    // ---- Layer 1 (K = 512; xproj columns n = t*64 + b) ----
    split_bf16<<<(G4 * Hc + 255) / 256, 256>>>(Wih1, Whi, Wlo, G4 * Hc);
    gemm_tc<<<gg, 256, GEMM_SMEM>>>(Whi, Wlo, hsHi, hsLo, bih1, bhh1, xproj, Hc);
    lstm_rec<<<NCTA, 256>>>(xproj, Whh1, hsHi, hsLo, 0);

    // ---- Layer 2 ----
    split_bf16<<<(G4 * Hc + 255) / 256, 256>>>(Wih2, Whi, Wlo, G4 * Hc);
    gemm_tc<<<gg, 256, GEMM_SMEM>>>(Whi, Wlo, hsHi, hsLo, bih2, bhh2, xproj, Hc);
    lstm_rec<<<NCTA, 256>>>(xproj, Whh2, hsHi, hsLo, 0);

    // ---- FC head ----
    fc1_kernel<<<16, 256>>>(hsHi, hsLo, W1, b1, h1);
    fc2_kernel<<<1, 64>>>(h1, W2, b2, (float*)d_out);
}